// round 15
// baseline (speedup 1.0000x reference)
#include <cuda_runtime.h>
#include <cstdint>

// ---------------- static scratch (no allocs allowed) ----------------
__device__ float g_xg[32768 * 3072];        // input-projection buffer (max 3H=3072)
__device__ float g_actB[32768 * 1024];      // raw GRU outputs (pre-LN)
__device__ unsigned g_hA[2][32 * 1024];     // group A hidden state (rows 0-31, tf32 bits)
__device__ unsigned g_hB[2][32 * 1024];     // group B hidden state (rows 32-63)
__device__ float g_psum[128 * 32768];       // per-CTA partial row sums
__device__ float g_psqs[128 * 32768];       // per-CTA partial row sumsq
__device__ float g_sum[32768];              // reduced row sums
__device__ float g_sqs[32768];              // reduced row sumsq
__device__ unsigned g_fA[128 * 32];         // group A progress flags (128B stride)
__device__ unsigned g_fB[128 * 32];         // group B progress flags

// ---------------- helpers ----------------
__device__ __forceinline__ unsigned f2tf(float x) {
    unsigned r; asm("cvt.rna.tf32.f32 %0, %1;" : "=r"(r) : "f"(x)); return r;
}
__device__ __forceinline__ void mma8(float* c, const unsigned* a, const unsigned* b) {
    asm volatile("mma.sync.aligned.m16n8k8.row.col.f32.tf32.tf32.f32 "
                 "{%0,%1,%2,%3}, {%4,%5,%6,%7}, {%8,%9}, {%0,%1,%2,%3};"
                 : "+f"(c[0]), "+f"(c[1]), "+f"(c[2]), "+f"(c[3])
                 : "r"(a[0]), "r"(a[1]), "r"(a[2]), "r"(a[3]),
                   "r"(b[0]), "r"(b[1]));
}
__device__ __forceinline__ float fast_sigmoid(float x) {
    return __fdividef(1.f, 1.f + __expf(-x));
}
__device__ __forceinline__ float fast_tanh(float x) {
    return 1.f - __fdividef(2.f, __expf(2.f * x) + 1.f);
}
__device__ __forceinline__ void cpa16(unsigned* smem_dst, const void* gsrc) {
    unsigned d = (unsigned)__cvta_generic_to_shared(smem_dst);
    asm volatile("cp.async.cg.shared.global [%0], [%1], 16;" :: "r"(d), "l"(gsrc));
}
#define CP_COMMIT() asm volatile("cp.async.commit_group;" ::: "memory")
template<int N> __device__ __forceinline__ void cp_wait() {
    asm volatile("cp.async.wait_group %0;" :: "n"(N) : "memory");
}

// ---------------- input-projection GEMM (128x128 tiles) with optional fused LN ----
template<int K, bool LN>
__global__ void __launch_bounds__(256) gemm_xg(const float* __restrict__ A,
                                               const float* __restrict__ W,
                                               int N,
                                               const float* __restrict__ gma,
                                               const float* __restrict__ bta,
                                               int nprev) {
    __shared__ unsigned As[128 * 36];
    __shared__ unsigned Bs[128 * 36];
    __shared__ float gS[K], bS[K];
    __shared__ float rmS[128], rsS[128];

    const int m0 = blockIdx.y * 128;
    const int n0 = blockIdx.x * 128;
    const int tid = threadIdx.x;
    const int lane = tid & 31, wid = tid >> 5;
    const int wm = (wid & 3) * 32, wn = (wid >> 2) * 64;

    if (blockIdx.x == 0 && blockIdx.y == 0 && tid < 128) {
        g_fA[tid * 32] = 0u;               // reset progress flags for the next rec
        g_fB[tid * 32] = 0u;
    }

    if (LN) {
        for (int i = tid; i < K; i += 256) { gS[i] = gma[i]; bS[i] = bta[i]; }
        if (tid < 128) {
            int m = m0 + tid;
            float s, q;
            if ((m & 511) >= 510) {
                s = 0.f; q = 0.f;
                for (int c = 0; c < nprev; c++) {
                    s += g_psum[(size_t)c * 32768 + m];
                    q += g_psqs[(size_t)c * 32768 + m];
                }
            } else {
                s = g_sum[m]; q = g_sqs[m];
            }
            float mean = s * (1.f / K);
            float var = q * (1.f / K) - mean * mean;
            rmS[tid] = mean;
            rsS[tid] = rsqrtf(var);
        }
        __syncthreads();
    }

    float acc[2][8][4];
#pragma unroll
    for (int i = 0; i < 2; i++)
#pragma unroll
        for (int j = 0; j < 8; j++)
#pragma unroll
            for (int k = 0; k < 4; k++) acc[i][j][k] = 0.f;

    const int lr = tid >> 3;
    const int lc = (tid & 7) * 4;

    for (int kc = 0; kc < K; kc += 32) {
#pragma unroll
        for (int i = 0; i < 4; i++) {
            int r = lr + i * 32;
            float4 v = *reinterpret_cast<const float4*>(&A[(size_t)(m0 + r) * K + kc + lc]);
            if (LN) {
                float mm = rmS[r], ss = rsS[r];
                int k = kc + lc;
                v.x = (v.x - mm) * ss * gS[k]     + bS[k];
                v.y = (v.y - mm) * ss * gS[k + 1] + bS[k + 1];
                v.z = (v.z - mm) * ss * gS[k + 2] + bS[k + 2];
                v.w = (v.w - mm) * ss * gS[k + 3] + bS[k + 3];
            }
            *reinterpret_cast<uint4*>(&As[r * 36 + lc]) =
                make_uint4(f2tf(v.x), f2tf(v.y), f2tf(v.z), f2tf(v.w));
        }
#pragma unroll
        for (int i = 0; i < 4; i++) {
            int r = lr + i * 32;
            float4 v = *reinterpret_cast<const float4*>(&W[(size_t)(n0 + r) * K + kc + lc]);
            *reinterpret_cast<uint4*>(&Bs[r * 36 + lc]) =
                make_uint4(f2tf(v.x), f2tf(v.y), f2tf(v.z), f2tf(v.w));
        }
        __syncthreads();
#pragma unroll
        for (int k8 = 0; k8 < 4; k8++) {
            const int kb = k8 * 8;
            unsigned a[2][4], b[8][2];
#pragma unroll
            for (int mf = 0; mf < 2; mf++) {
                int rb = wm + mf * 16 + (lane >> 2);
                a[mf][0] = As[rb * 36 + kb + (lane & 3)];
                a[mf][1] = As[(rb + 8) * 36 + kb + (lane & 3)];
                a[mf][2] = As[rb * 36 + kb + (lane & 3) + 4];
                a[mf][3] = As[(rb + 8) * 36 + kb + (lane & 3) + 4];
            }
#pragma unroll
            for (int nf = 0; nf < 8; nf++) {
                int cb = wn + nf * 8 + (lane >> 2);
                b[nf][0] = Bs[cb * 36 + kb + (lane & 3)];
                b[nf][1] = Bs[cb * 36 + kb + (lane & 3) + 4];
            }
#pragma unroll
            for (int mf = 0; mf < 2; mf++)
#pragma unroll
                for (int nf = 0; nf < 8; nf++)
                    mma8(acc[mf][nf], a[mf], b[nf]);
        }
        __syncthreads();
    }
#pragma unroll
    for (int mf = 0; mf < 2; mf++)
#pragma unroll
        for (int nf = 0; nf < 8; nf++) {
            int row = m0 + wm + mf * 16 + (lane >> 2);
            int col = n0 + wn + nf * 8 + 2 * (lane & 3);
            g_xg[(size_t)row * N + col]     = acc[mf][nf][0];
            g_xg[(size_t)row * N + col + 1] = acc[mf][nf][1];
            g_xg[(size_t)(row + 8) * N + col]     = acc[mf][nf][2];
            g_xg[(size_t)(row + 8) * N + col + 1] = acc[mf][nf][3];
        }
}

// ---------------- persistent GRU recurrence: two-phase batch-split pipeline -------
// grid = H/8 CTAs, 256 threads. The 64-row batch splits into two INDEPENDENT
// 32-row recurrences A (rows 0-31) and B (rows 32-63). Each step runs phase A
// then phase B; each group's wait sits a half-step after the matching publishes
// (skew hidden), and each group's chunk prime issues under the other group's
// epilogue (pipeline fill hidden). Per-group mainloop: 8 warps (mi = wid&1 ->
// 16-row m-tile, kq = wid>>1 -> k-quarter), cp.async D=3 warp-private slots,
// XOR-swizzled. kq fold + epilogue arithmetic bitwise-identical to round 13.
template<int H>
__global__ void __launch_bounds__(256, 1) gru_rec(const float* __restrict__ Whh) {
    constexpr int NCH = H / 128;
    constexpr int NC  = H / 8;           // == gridDim.x  (<= 128)
    constexpr int D   = 3;
    constexpr int P   = NCH < D ? NCH : D;
    extern __shared__ unsigned char smem_raw[];
    unsigned* Wf  = reinterpret_cast<unsigned*>(smem_raw);     // [H/8][3][64] packed B
    unsigned* ApA = Wf + (H / 8) * 192;                        // 8 warps x D x 512 words
    unsigned* ApB = ApA + 8 * D * 512;
    float* hgS = reinterpret_cast<float*>(ApB + 8 * D * 512);  // 4 x [32][40]

    const float* xg = g_xg;
    float* y = g_actB;
    const int tid = threadIdx.x;
    const int lane = tid & 31, wid = tid >> 5;
    const int cta = blockIdx.x;
    const int c0 = cta * 8;
    const int q = lane >> 2, r4 = lane & 3;
    const int mi = wid & 1;              // m-half within group: rows mi*16..mi*16+15
    const int kq = wid >> 1;             // k-quarter within each 128-chunk
    const int kb0 = kq * 32;

    // one-time: Whh slice -> SMEM in fragment-packed tf32 order (shared by groups)
    {
        constexpr int nf4 = H / 4;
        for (int idx = tid; idx < 24 * nf4; idx += 256) {
            int nn = idx / nf4;
            int c4 = (idx % nf4) * 4;
            int gate = nn >> 3, j = nn & 7;
            float4 v = *reinterpret_cast<const float4*>(&Whh[(size_t)(gate * H + c0 + j) * H + c4]);
            int kb8 = c4 >> 3;
            int half = (c4 >> 2) & 1;
            unsigned* base = Wf + (kb8 * 3 + gate) * 64 + j * 8 + half;
            base[0] = f2tf(v.x); base[2] = f2tf(v.y);
            base[4] = f2tf(v.z); base[6] = f2tf(v.w);
        }
    }
    __syncthreads();

    const int col = tid & 7;             // epilogue: own column
    const int brow = tid >> 3;           // epilogue: local batch row 0..31
    float hlA = 0.f, hlB = 0.f;
    float pxrA, pxzA, pxnA, pxrB, pxzB, pxnB;

#define PF_XG(GRP, TT, PXR, PXZ, PXN) do { \
        int b_ = (GRP) * 32 + brow; \
        const float* xrow = xg + ((size_t)b_ * 512 + (TT)) * (size_t)(3 * H); \
        PXR = __ldcs(xrow + c0 + col); \
        PXZ = __ldcs(xrow + H + c0 + col); \
        PXN = __ldcs(xrow + 2 * H + c0 + col); \
    } while (0)

    PF_XG(0, 0, pxrA, pxzA, pxnA);
    PF_XG(1, 0, pxrB, pxzB, pxnB);

    unsigned* AwA = ApA + wid * (D * 512);
    unsigned* AwB = ApB + wid * (D * 512);

#define ISSUE_CHUNK(HSRC, AW, CH, SLOT) do { \
        unsigned* _sl = (AW) + (SLOT) * 512; \
        _Pragma("unroll") \
        for (int i_ = 0; i_ < 4; i_++) { \
            int task_ = lane + i_ * 32; \
            int row_ = task_ >> 3, unit_ = task_ & 7; \
            cpa16(_sl + row_ * 32 + ((unit_ ^ (row_ & 7)) << 2), \
                  &(HSRC)[(size_t)(mi * 16 + row_) * H + (CH) * 128 + kb0 + unit_ * 4]); \
        } \
        CP_COMMIT(); \
    } while (0)

#define PRIME(HSRC, AW) do { \
        _Pragma("unroll") \
        for (int s_ = 0; s_ < P; s_++) ISSUE_CHUNK(HSRC, AW, s_, s_); \
    } while (0)

#define MAINLOOP(HSRC, AW, ACC) do { \
        for (int ch = 0; ch < NCH; ch++) { \
            const int rem = NCH - 1 - ch; \
            if (rem >= 2)      { cp_wait<2>(); } \
            else if (rem == 1) { cp_wait<1>(); } \
            else               { cp_wait<0>(); } \
            __syncwarp(); \
            const unsigned* Ab = (AW) + (ch % D) * 512; \
            _Pragma("unroll") \
            for (int k8 = 0; k8 < 4; k8++) { \
                const int u0 = k8 * 2; \
                const int sw0 = ((u0 ^ q) << 2) + r4; \
                const int sw1 = (((u0 + 1) ^ q) << 2) + r4; \
                const int g8 = ch * 16 + kq * 4 + k8; \
                unsigned a0[4]; \
                a0[0] = Ab[q * 32 + sw0]; \
                a0[1] = Ab[(q + 8) * 32 + sw0]; \
                a0[2] = Ab[q * 32 + sw1]; \
                a0[3] = Ab[(q + 8) * 32 + sw1]; \
                _Pragma("unroll") \
                for (int nf = 0; nf < 3; nf++) { \
                    uint2 bb = *reinterpret_cast<const uint2*>(&Wf[(g8 * 3 + nf) * 64 + lane * 2]); \
                    unsigned bfr[2] = {bb.x, bb.y}; \
                    mma8(ACC[nf], a0, bfr); \
                } \
            } \
            if (ch + D < NCH) ISSUE_CHUNK(HSRC, AW, ch + D, ch % D); \
        } \
    } while (0)

#define STORE_PART(ACC) do { \
        float* dst = hgS + kq * 1280; \
        _Pragma("unroll") \
        for (int nf = 0; nf < 3; nf++) { \
            int row = mi * 16 + q; \
            int cc = nf * 8 + 2 * r4; \
            dst[row * 40 + cc]           = ACC[nf][0]; \
            dst[row * 40 + cc + 1]       = ACC[nf][1]; \
            dst[(row + 8) * 40 + cc]     = ACC[nf][2]; \
            dst[(row + 8) * 40 + cc + 1] = ACC[nf][3]; \
        } \
    } while (0)

#define EPILOGUE(GRP, PXR, PXZ, PXN, HL, HDST) do { \
        int b = brow; \
        float hr = hgS[b * 40 + col]      + hgS[1280 + b * 40 + col] \
                 + hgS[2560 + b * 40 + col]      + hgS[3840 + b * 40 + col]; \
        float hz = hgS[b * 40 + 8 + col]  + hgS[1280 + b * 40 + 8 + col] \
                 + hgS[2560 + b * 40 + 8 + col]  + hgS[3840 + b * 40 + 8 + col]; \
        float hn = hgS[b * 40 + 16 + col] + hgS[1280 + b * 40 + 16 + col] \
                 + hgS[2560 + b * 40 + 16 + col] + hgS[3840 + b * 40 + 16 + col]; \
        float r = fast_sigmoid(PXR + hr); \
        float z = fast_sigmoid(PXZ + hz); \
        float n = fast_tanh(PXN + r * hn); \
        float h2 = (1.f - z) * n + z * HL; \
        HL = h2; \
        size_t m = (size_t)((GRP) * 32 + b) * 512 + t; \
        y[m * (size_t)H + c0 + col] = h2; \
        __stcg(&(HDST)[b * H + c0 + col], f2tf(h2)); \
        float s = h2, qq = h2 * h2; \
        _Pragma("unroll") \
        for (int o = 4; o > 0; o >>= 1) { \
            s  += __shfl_down_sync(0xffffffffu, s, o, 8); \
            qq += __shfl_down_sync(0xffffffffu, qq, o, 8); \
        } \
        if (col == 0) { \
            __stcg(&g_psum[(size_t)cta * 32768 + m], s); \
            __stcg(&g_psqs[(size_t)cta * 32768 + m], qq); \
        } \
    } while (0)

#define SPIN(FLAGS, VAL) do { \
        unsigned v_; \
        do { \
            asm volatile("ld.acquire.gpu.u32 %0, [%1];" \
                         : "=r"(v_) : "l"(&(FLAGS)[tid * 32]) : "memory"); \
        } while (v_ < (unsigned)(VAL)); \
    } while (0)

#define PUBLISH(FLAGS, VAL) \
        asm volatile("st.release.gpu.u32 [%0], %1;" \
                     :: "l"(&(FLAGS)[cta * 32]), "r"((unsigned)(VAL)) : "memory")

    for (int t = 0; t < 512; t++) {
        // ================= phase A =================
        float acc[3][4];
#pragma unroll
        for (int nf = 0; nf < 3; nf++)
#pragma unroll
            for (int k = 0; k < 4; k++) acc[nf][k] = 0.f;
        if (t > 0) MAINLOOP(g_hA[t & 1], AwA, acc);
        STORE_PART(acc);
        // waitB(t): slack = phase A of this iteration (skew hidden)
        if (tid < NC) {
            SPIN(g_fB, t);
        } else if (wid >= 4 && t >= 2) {
            // shadow: reduce LN partials of step t-2 (all 64 rows)
            int r = cta + (wid - 4) * NC;
            if (r < 64) {
                int m = r * 512 + (t - 2);
                float s = 0.f, qv = 0.f;
                for (int c = lane; c < NC; c += 32) {
                    s  += __ldcg(&g_psum[(size_t)c * 32768 + m]);
                    qv += __ldcg(&g_psqs[(size_t)c * 32768 + m]);
                }
#pragma unroll
                for (int o = 16; o > 0; o >>= 1) {
                    s  += __shfl_xor_sync(0xffffffffu, s, o);
                    qv += __shfl_xor_sync(0xffffffffu, qv, o);
                }
                if (lane == 0) { __stcg(&g_sum[m], s); __stcg(&g_sqs[m], qv); }
            }
        }
        __syncthreads();
        if (t > 0) PRIME(g_hB[t & 1], AwB);     // B's fill flies under epilogue A
        EPILOGUE(0, pxrA, pxzA, pxnA, hlA, g_hA[(t + 1) & 1]);
        if (t < 511) PF_XG(0, t + 1, pxrA, pxzA, pxnA);
        __syncthreads();
        if (t < 511 && tid == 0) PUBLISH(g_fA, t + 1);

        // ================= phase B =================
#pragma unroll
        for (int nf = 0; nf < 3; nf++)
#pragma unroll
            for (int k = 0; k < 4; k++) acc[nf][k] = 0.f;
        if (t > 0) MAINLOOP(g_hB[t & 1], AwB, acc);
        STORE_PART(acc);
        // waitA(t+1): slack = phase B mainloop (skew hidden)
        if (t < 511) {
            if (tid < NC) SPIN(g_fA, t + 1);
            __syncthreads();
            PRIME(g_hA[(t + 1) & 1], AwA);      // A's fill flies under epilogue B
        } else {
            __syncthreads();
        }
        EPILOGUE(1, pxrB, pxzB, pxnB, hlB, g_hB[(t + 1) & 1]);
        if (t < 511) PF_XG(1, t + 1, pxrB, pxzB, pxnB);
        __syncthreads();
        if (t < 511 && tid == 0) PUBLISH(g_fB, t + 1);
    }
#undef PF_XG
#undef ISSUE_CHUNK
#undef PRIME
#undef MAINLOOP
#undef STORE_PART
#undef EPILOGUE
#undef SPIN
#undef PUBLISH
}

// ---------------- final LayerNorm (H=128, eps=0) ----------------
template<int H>
__global__ void __launch_bounds__(128) ln_k(const float* __restrict__ gw,
                                            const float* __restrict__ bw,
                                            float* __restrict__ outp) {
    constexpr int PER = H / 128;
    __shared__ float red[8];
    const int row = blockIdx.x, tid = threadIdx.x;
    const float* p = g_actB + (size_t)row * H;
    float v[PER];
    float s = 0.f;
#pragma unroll
    for (int i = 0; i < PER; i++) { v[i] = p[tid + i * 128]; s += v[i]; }
#pragma unroll
    for (int o = 16; o > 0; o >>= 1) s += __shfl_xor_sync(0xffffffffu, s, o);
    if ((tid & 31) == 0) red[tid >> 5] = s;
    __syncthreads();
    float mean = (red[0] + red[1] + red[2] + red[3]) * (1.f / H);
    float s2 = 0.f;
#pragma unroll
    for (int i = 0; i < PER; i++) { float d = v[i] - mean; s2 += d * d; }
#pragma unroll
    for (int o = 16; o > 0; o >>= 1) s2 += __shfl_xor_sync(0xffffffffu, s2, o);
    if ((tid & 31) == 0) red[4 + (tid >> 5)] = s2;
    __syncthreads();
    float var = (red[4] + red[5] + red[6] + red[7]) * (1.f / H);
    float inv = rsqrtf(var);
#pragma unroll
    for (int i = 0; i < PER; i++) {
        int c = tid + i * 128;
        outp[(size_t)row * H + c] = (v[i] - mean) * inv * gw[c] + bw[c];
    }
}

// ---------------- driver ----------------
template<int H>
static void launch_rec(const float* Whh) {
    constexpr int SM = sizeof(unsigned) * ((H / 8) * 192 + 2 * 8 * 3 * 512)
                     + sizeof(float) * (4 * 32 * 40);
    cudaFuncSetAttribute(gru_rec<H>, cudaFuncAttributeMaxDynamicSharedMemorySize, SM);
    gru_rec<H><<<H / 8, 256, SM>>>(Whh);
}

extern "C" void kernel_launch(void* const* d_in, const int* in_sizes, int n_in,
                              void* d_out, int out_size) {
    (void)in_sizes; (void)n_in; (void)out_size;
    const float* x = (const float*)d_in[0];
    const float* Wih[6]; const float* Whh[6]; const float* gw[6]; const float* bw[6];
    for (int l = 0; l < 6; l++) {
        Wih[l] = (const float*)d_in[1 + 4 * l];
        Whh[l] = (const float*)d_in[2 + 4 * l];
        gw[l]  = (const float*)d_in[3 + 4 * l];
        bw[l]  = (const float*)d_in[4 + 4 * l];
    }
    float* actB;
    cudaGetSymbolAddress((void**)&actB, g_actB);

    static const int DIN[6] = {128, 256, 512, 1024, 512, 256};
    static const int HH[6]  = {256, 512, 1024, 512, 256, 128};

    for (int l = 0; l < 6; l++) {
        const int K = DIN[l], H = HH[l], N = 3 * H;
        const float* A = (l == 0) ? x : (const float*)actB;
        const float* gma = (l == 0) ? nullptr : gw[l - 1];
        const float* bta = (l == 0) ? nullptr : bw[l - 1];
        const int nprev = (l == 0) ? 0 : HH[l - 1] / 8;
        dim3 grid(N / 128, 256);
        if (l == 0) {
            gemm_xg<128, false><<<grid, 256>>>(A, Wih[l], N, gma, bta, nprev);
        } else {
            switch (K) {
                case 256:  gemm_xg<256, true><<<grid, 256>>>(A, Wih[l], N, gma, bta, nprev); break;
                case 512:  gemm_xg<512, true><<<grid, 256>>>(A, Wih[l], N, gma, bta, nprev); break;
                case 1024: gemm_xg<1024, true><<<grid, 256>>>(A, Wih[l], N, gma, bta, nprev); break;
            }
        }
        switch (H) {
            case 128:  launch_rec<128>(Whh[l]); break;
            case 256:  launch_rec<256>(Whh[l]); break;
            case 512:  launch_rec<512>(Whh[l]); break;
            case 1024: launch_rec<1024>(Whh[l]); break;
        }
    }
    ln_k<128><<<32768, 128>>>(gw[5], bw[5], (float*)d_out);
}

// round 16
// speedup vs baseline: 1.1144x; 1.1144x over previous
#include <cuda_runtime.h>
#include <cstdint>

// ---------------- static scratch (no allocs allowed) ----------------
__device__ float g_xg[32768 * 3072];        // input-projection buffer (max 3H=3072)
__device__ float g_actB[32768 * 1024];      // raw GRU outputs (pre-LN)
__device__ unsigned g_h[2][64 * 1024];      // double-buffered hidden state (tf32 bits)
__device__ float g_psum[128 * 32768];       // per-CTA partial row sums
__device__ float g_psqs[128 * 32768];       // per-CTA partial row sumsq
__device__ float g_sum[32768];              // reduced row sums
__device__ float g_sqs[32768];              // reduced row sumsq
__device__ unsigned g_arr[128 * 32];        // decentralized barrier slots (128B stride)

// ---------------- helpers ----------------
__device__ __forceinline__ unsigned f2tf(float x) {
    unsigned r; asm("cvt.rna.tf32.f32 %0, %1;" : "=r"(r) : "f"(x)); return r;
}
__device__ __forceinline__ void mma8(float* c, const unsigned* a, const unsigned* b) {
    asm volatile("mma.sync.aligned.m16n8k8.row.col.f32.tf32.tf32.f32 "
                 "{%0,%1,%2,%3}, {%4,%5,%6,%7}, {%8,%9}, {%0,%1,%2,%3};"
                 : "+f"(c[0]), "+f"(c[1]), "+f"(c[2]), "+f"(c[3])
                 : "r"(a[0]), "r"(a[1]), "r"(a[2]), "r"(a[3]),
                   "r"(b[0]), "r"(b[1]));
}
__device__ __forceinline__ float fast_sigmoid(float x) {
    return __fdividef(1.f, 1.f + __expf(-x));
}
__device__ __forceinline__ float fast_tanh(float x) {
    return 1.f - __fdividef(2.f, __expf(2.f * x) + 1.f);
}
__device__ __forceinline__ void cpa16(unsigned* smem_dst, const void* gsrc) {
    unsigned d = (unsigned)__cvta_generic_to_shared(smem_dst);
    asm volatile("cp.async.cg.shared.global [%0], [%1], 16;" :: "r"(d), "l"(gsrc));
}
#define CP_COMMIT() asm volatile("cp.async.commit_group;" ::: "memory")
template<int N> __device__ __forceinline__ void cp_wait() {
    asm volatile("cp.async.wait_group %0;" :: "n"(N) : "memory");
}

// ---------------- input-projection GEMM (128x128 tiles, reg-prefetch DB) ----------
// C[m,n] = sum_k LN(A[m,k]) * W[n,k]. Next k-stage's global loads issue BEFORE the
// mma on the current stage (register double-buffer) -> L2/DRAM latency hidden.
// LN applied at store time (same arithmetic as round 13 -> g_xg bit-identical).
template<int K, bool LN>
__global__ void __launch_bounds__(256) gemm_xg(const float* __restrict__ A,
                                               const float* __restrict__ W,
                                               int N,
                                               const float* __restrict__ gma,
                                               const float* __restrict__ bta,
                                               int nprev) {
    __shared__ unsigned As[128 * 36];
    __shared__ unsigned Bs[128 * 36];
    __shared__ float gS[K], bS[K];
    __shared__ float rmS[128], rsS[128];

    const int m0 = blockIdx.y * 128;
    const int n0 = blockIdx.x * 128;
    const int tid = threadIdx.x;
    const int lane = tid & 31, wid = tid >> 5;
    const int wm = (wid & 3) * 32, wn = (wid >> 2) * 64;

    if (blockIdx.x == 0 && blockIdx.y == 0 && tid < 128)
        g_arr[tid * 32] = 0u;              // reset barrier slots for the next rec

    if (LN) {
        for (int i = tid; i < K; i += 256) { gS[i] = gma[i]; bS[i] = bta[i]; }
        if (tid < 128) {
            int m = m0 + tid;
            float s, q;
            if ((m & 511) >= 510) {
                s = 0.f; q = 0.f;
                for (int c = 0; c < nprev; c++) {
                    s += g_psum[(size_t)c * 32768 + m];
                    q += g_psqs[(size_t)c * 32768 + m];
                }
            } else {
                s = g_sum[m]; q = g_sqs[m];
            }
            float mean = s * (1.f / K);
            float var = q * (1.f / K) - mean * mean;
            rmS[tid] = mean;
            rsS[tid] = rsqrtf(var);
        }
        __syncthreads();
    }

    float acc[2][8][4];
#pragma unroll
    for (int i = 0; i < 2; i++)
#pragma unroll
        for (int j = 0; j < 8; j++)
#pragma unroll
            for (int k = 0; k < 4; k++) acc[i][j][k] = 0.f;

    const int lr = tid >> 3;
    const int lc = (tid & 7) * 4;

    float4 va[4], vb[4];
#define G_LOAD(KC) do { \
        _Pragma("unroll") \
        for (int i_ = 0; i_ < 4; i_++) { \
            va[i_] = *reinterpret_cast<const float4*>(&A[(size_t)(m0 + lr + i_ * 32) * K + (KC) + lc]); \
            vb[i_] = *reinterpret_cast<const float4*>(&W[(size_t)(n0 + lr + i_ * 32) * K + (KC) + lc]); \
        } \
    } while (0)

    G_LOAD(0);

    for (int kc = 0; kc < K; kc += 32) {
        // convert (+LN) and store the prefetched stage
#pragma unroll
        for (int i = 0; i < 4; i++) {
            int r = lr + i * 32;
            float4 v = va[i];
            if (LN) {
                float mm = rmS[r], ss = rsS[r];
                int k = kc + lc;
                v.x = (v.x - mm) * ss * gS[k]     + bS[k];
                v.y = (v.y - mm) * ss * gS[k + 1] + bS[k + 1];
                v.z = (v.z - mm) * ss * gS[k + 2] + bS[k + 2];
                v.w = (v.w - mm) * ss * gS[k + 3] + bS[k + 3];
            }
            *reinterpret_cast<uint4*>(&As[r * 36 + lc]) =
                make_uint4(f2tf(v.x), f2tf(v.y), f2tf(v.z), f2tf(v.w));
            float4 w = vb[i];
            *reinterpret_cast<uint4*>(&Bs[r * 36 + lc]) =
                make_uint4(f2tf(w.x), f2tf(w.y), f2tf(w.z), f2tf(w.w));
        }
        __syncthreads();
        if (kc + 32 < K) G_LOAD(kc + 32);  // next stage in flight under the mma
#pragma unroll
        for (int k8 = 0; k8 < 4; k8++) {
            const int kb = k8 * 8;
            unsigned a[2][4], b[8][2];
#pragma unroll
            for (int mf = 0; mf < 2; mf++) {
                int rb = wm + mf * 16 + (lane >> 2);
                a[mf][0] = As[rb * 36 + kb + (lane & 3)];
                a[mf][1] = As[(rb + 8) * 36 + kb + (lane & 3)];
                a[mf][2] = As[rb * 36 + kb + (lane & 3) + 4];
                a[mf][3] = As[(rb + 8) * 36 + kb + (lane & 3) + 4];
            }
#pragma unroll
            for (int nf = 0; nf < 8; nf++) {
                int cb = wn + nf * 8 + (lane >> 2);
                b[nf][0] = Bs[cb * 36 + kb + (lane & 3)];
                b[nf][1] = Bs[cb * 36 + kb + (lane & 3) + 4];
            }
#pragma unroll
            for (int mf = 0; mf < 2; mf++)
#pragma unroll
                for (int nf = 0; nf < 8; nf++)
                    mma8(acc[mf][nf], a[mf], b[nf]);
        }
        __syncthreads();
    }
#undef G_LOAD
#pragma unroll
    for (int mf = 0; mf < 2; mf++)
#pragma unroll
        for (int nf = 0; nf < 8; nf++) {
            int row = m0 + wm + mf * 16 + (lane >> 2);
            int col = n0 + wn + nf * 8 + 2 * (lane & 3);
            g_xg[(size_t)row * N + col]     = acc[mf][nf][0];
            g_xg[(size_t)row * N + col + 1] = acc[mf][nf][1];
            g_xg[(size_t)(row + 8) * N + col]     = acc[mf][nf][2];
            g_xg[(size_t)(row + 8) * N + col + 1] = acc[mf][nf][3];
        }
}

// ---------------- persistent GRU recurrence (round-13, cp.async D=4 pipeline) -----
// grid = H/8 CTAs, 256 threads, 8 warps: warp (mi = wid&1, kq = wid>>1).
// A staged via cp.async into warp-private XOR-swizzled 4KB slots, 4 deep: steady
// state keeps 3 chunks in flight -> h-load latency hidden behind 3 chunks of mma.
// hgS merge buffers ALIAS the A region. Decentralized barrier + shadow LN.
template<int H>
__global__ void __launch_bounds__(256, 1) gru_rec(const float* __restrict__ Whh) {
    constexpr int NCH = H / 128;         // 128-wide global chunks (kq covers 32 each)
    constexpr int NC  = H / 8;           // == gridDim.x  (<= 128)
    constexpr int D   = 4;               // pipeline depth (slots per warp)
    constexpr int P   = NCH < D ? NCH : D;
    extern __shared__ unsigned char smem_raw[];
    unsigned* Wf = reinterpret_cast<unsigned*>(smem_raw);      // [H/8][3][64] packed B
    unsigned* Apriv = Wf + (H / 8) * 192;                      // 8 warps x D x 1024 words
    float* hgS = reinterpret_cast<float*>(Apriv);              // ALIAS: 4 x [64][40]

    const float* xg = g_xg;
    float* y = g_actB;
    const int tid = threadIdx.x;
    const int lane = tid & 31, wid = tid >> 5;
    const int cta = blockIdx.x;
    const int c0 = cta * 8;
    const int q = lane >> 2, r4 = lane & 3;
    const int mi = wid & 1;              // m-half: rows mi*32..mi*32+31
    const int kq = wid >> 1;             // k-quarter within each 128-chunk
    const int kb0 = kq * 32;             // this warp's k-offset in each chunk

    // one-time: Whh slice -> SMEM in fragment-packed tf32 order
    {
        constexpr int nf4 = H / 4;
        for (int idx = tid; idx < 24 * nf4; idx += 256) {
            int nn = idx / nf4;               // 0..23 : gate*8 + j
            int c4 = (idx % nf4) * 4;         // k, multiple of 4
            int gate = nn >> 3, j = nn & 7;
            float4 v = *reinterpret_cast<const float4*>(&Whh[(size_t)(gate * H + c0 + j) * H + c4]);
            int kb8 = c4 >> 3;
            int half = (c4 >> 2) & 1;
            unsigned* base = Wf + (kb8 * 3 + gate) * 64 + j * 8 + half;
            base[0] = f2tf(v.x); base[2] = f2tf(v.y);
            base[4] = f2tf(v.z); base[6] = f2tf(v.w);
        }
    }
    __syncthreads();

    const int col = tid & 7;             // epilogue: own column
    const int brow = tid >> 3;           // epilogue: batch rows brow, brow+32
    float hl[2] = {0.f, 0.f};
    float pxr[2], pxz[2], pxn[2];

#define PF_XG(TT) do { \
        _Pragma("unroll") \
        for (int it = 0; it < 2; it++) { \
            int b_ = brow + it * 32; \
            const float* xrow = xg + ((size_t)b_ * 512 + (TT)) * (size_t)(3 * H); \
            pxr[it] = __ldcs(xrow + c0 + col); \
            pxz[it] = __ldcs(xrow + H + c0 + col); \
            pxn[it] = __ldcs(xrow + 2 * H + c0 + col); \
        } } while (0)

    PF_XG(0);

    unsigned* AwBase = Apriv + wid * (D * 1024);

#define ISSUE_CHUNK(CH, SLOT) do { \
        unsigned* _sl = AwBase + (SLOT) * 1024; \
        _Pragma("unroll") \
        for (int i_ = 0; i_ < 8; i_++) { \
            int task_ = lane + i_ * 32; \
            int row_ = task_ >> 3, unit_ = task_ & 7; \
            cpa16(_sl + row_ * 32 + ((unit_ ^ (row_ & 7)) << 2), \
                  &hsrc[(size_t)(mi * 32 + row_) * H + (CH) * 128 + kb0 + unit_ * 4]); \
        } \
        CP_COMMIT(); \
    } while (0)

    for (int t = 0; t < 512; t++) {
        float acc[2][3][4];
#pragma unroll
        for (int mf = 0; mf < 2; mf++)
#pragma unroll
            for (int nf = 0; nf < 3; nf++)
#pragma unroll
                for (int k = 0; k < 4; k++) acc[mf][nf][k] = 0.f;

        if (t > 0) {
            const unsigned* hsrc = g_h[t & 1];
            // prime P chunks
#pragma unroll
            for (int s = 0; s < P; s++) ISSUE_CHUNK(s, s);

            for (int ch = 0; ch < NCH; ch++) {
                const int rem = NCH - 1 - ch;
                if (rem >= P)      { cp_wait<P - 1>(); }
                else if (rem == 3) { cp_wait<3>(); }
                else if (rem == 2) { cp_wait<2>(); }
                else if (rem == 1) { cp_wait<1>(); }
                else               { cp_wait<0>(); }
                __syncwarp();
                const unsigned* Ab = AwBase + (ch % D) * 1024;
#pragma unroll
                for (int k8 = 0; k8 < 4; k8++) {
                    const int u0 = k8 * 2;
                    const int sw0 = ((u0 ^ q) << 2) + r4;
                    const int sw1 = (((u0 + 1) ^ q) << 2) + r4;
                    const int g8 = ch * 16 + kq * 4 + k8;     // global k8 index
                    unsigned a0[4], a1[4];
                    a0[0] = Ab[q * 32 + sw0];
                    a0[1] = Ab[(q + 8) * 32 + sw0];
                    a0[2] = Ab[q * 32 + sw1];
                    a0[3] = Ab[(q + 8) * 32 + sw1];
                    a1[0] = Ab[(q + 16) * 32 + sw0];
                    a1[1] = Ab[(q + 24) * 32 + sw0];
                    a1[2] = Ab[(q + 16) * 32 + sw1];
                    a1[3] = Ab[(q + 24) * 32 + sw1];
#pragma unroll
                    for (int nf = 0; nf < 3; nf++) {
                        uint2 bb = *reinterpret_cast<const uint2*>(&Wf[(g8 * 3 + nf) * 64 + lane * 2]);
                        unsigned bfr[2] = {bb.x, bb.y};
                        mma8(acc[0][nf], a0, bfr);
                        mma8(acc[1][nf], a1, bfr);
                    }
                }
                if (ch + P < NCH) ISSUE_CHUNK(ch + P, (ch + P) % D);
            }
        }
        __syncthreads();                 // A slots dead before hgS alias writes

        // ---- all warps store their K-partials into their kq buffer ----
        {
            float* dst = hgS + kq * 2560;
#pragma unroll
            for (int mf = 0; mf < 2; mf++)
#pragma unroll
                for (int nf = 0; nf < 3; nf++) {
                    int row = mi * 32 + mf * 16 + q;
                    int cc = nf * 8 + 2 * r4;
                    dst[row * 40 + cc]           = acc[mf][nf][0];
                    dst[row * 40 + cc + 1]       = acc[mf][nf][1];
                    dst[(row + 8) * 40 + cc]     = acc[mf][nf][2];
                    dst[(row + 8) * 40 + cc + 1] = acc[mf][nf][3];
                }
        }
        __syncthreads();

        // ---- gate epilogue: sums 4 kq buffers in kq order ----
        unsigned* hdst = g_h[(t + 1) & 1];
#pragma unroll
        for (int it = 0; it < 2; it++) {
            int b = brow + it * 32;
            float hr = hgS[b * 40 + col]      + hgS[2560 + b * 40 + col]
                     + hgS[5120 + b * 40 + col]      + hgS[7680 + b * 40 + col];
            float hz = hgS[b * 40 + 8 + col]  + hgS[2560 + b * 40 + 8 + col]
                     + hgS[5120 + b * 40 + 8 + col]  + hgS[7680 + b * 40 + 8 + col];
            float hn = hgS[b * 40 + 16 + col] + hgS[2560 + b * 40 + 16 + col]
                     + hgS[5120 + b * 40 + 16 + col] + hgS[7680 + b * 40 + 16 + col];
            float r = fast_sigmoid(pxr[it] + hr);
            float z = fast_sigmoid(pxz[it] + hz);
            float n = fast_tanh(pxn[it] + r * hn);
            float h2 = (1.f - z) * n + z * hl[it];
            hl[it] = h2;
            size_t m = (size_t)b * 512 + t;
            y[m * (size_t)H + c0 + col] = h2;
            __stcg(&hdst[b * H + c0 + col], f2tf(h2));
            float s = h2, qq = h2 * h2;
#pragma unroll
            for (int o = 4; o > 0; o >>= 1) {
                s  += __shfl_down_sync(0xffffffffu, s, o, 8);
                qq += __shfl_down_sync(0xffffffffu, qq, o, 8);
            }
            if (col == 0) {
                __stcg(&g_psum[(size_t)cta * 32768 + m], s);
                __stcg(&g_psqs[(size_t)cta * 32768 + m], qq);
            }
        }

        if (t < 511) {
            PF_XG(t + 1);                  // independent of h; hides under barrier
            __syncthreads();               // h stores + hgS reads complete
            if (tid == 0)
                asm volatile("st.release.gpu.u32 [%0], %1;"
                             :: "l"(&g_arr[cta * 32]), "r"((unsigned)(t + 1)) : "memory");
            if (tid < NC) {
                unsigned v;
                do {
                    asm volatile("ld.acquire.gpu.u32 %0, [%1];"
                                 : "=r"(v) : "l"(&g_arr[tid * 32]) : "memory");
                } while (v < (unsigned)(t + 1));
            } else if (wid >= 4 && t >= 1) {
                // shadow: reduce LN partials of step t-1 while pollers spin
                int r = cta + (wid - 4) * NC;
                if (r < 64) {
                    int m = r * 512 + (t - 1);
                    float s = 0.f, qv = 0.f;
                    for (int c = lane; c < NC; c += 32) {
                        s  += __ldcg(&g_psum[(size_t)c * 32768 + m]);
                        qv += __ldcg(&g_psqs[(size_t)c * 32768 + m]);
                    }
#pragma unroll
                    for (int o = 16; o > 0; o >>= 1) {
                        s  += __shfl_xor_sync(0xffffffffu, s, o);
                        qv += __shfl_xor_sync(0xffffffffu, qv, o);
                    }
                    if (lane == 0) { __stcg(&g_sum[m], s); __stcg(&g_sqs[m], qv); }
                }
            }
            __syncthreads();
        }
    }
#undef PF_XG
#undef ISSUE_CHUNK
}

// ---------------- final LayerNorm (H=128, eps=0) ----------------
template<int H>
__global__ void __launch_bounds__(128) ln_k(const float* __restrict__ gw,
                                            const float* __restrict__ bw,
                                            float* __restrict__ outp) {
    constexpr int PER = H / 128;
    __shared__ float red[8];
    const int row = blockIdx.x, tid = threadIdx.x;
    const float* p = g_actB + (size_t)row * H;
    float v[PER];
    float s = 0.f;
#pragma unroll
    for (int i = 0; i < PER; i++) { v[i] = p[tid + i * 128]; s += v[i]; }
#pragma unroll
    for (int o = 16; o > 0; o >>= 1) s += __shfl_xor_sync(0xffffffffu, s, o);
    if ((tid & 31) == 0) red[tid >> 5] = s;
    __syncthreads();
    float mean = (red[0] + red[1] + red[2] + red[3]) * (1.f / H);
    float s2 = 0.f;
#pragma unroll
    for (int i = 0; i < PER; i++) { float d = v[i] - mean; s2 += d * d; }
#pragma unroll
    for (int o = 16; o > 0; o >>= 1) s2 += __shfl_xor_sync(0xffffffffu, s2, o);
    if ((tid & 31) == 0) red[4 + (tid >> 5)] = s2;
    __syncthreads();
    float var = (red[4] + red[5] + red[6] + red[7]) * (1.f / H);
    float inv = rsqrtf(var);
#pragma unroll
    for (int i = 0; i < PER; i++) {
        int c = tid + i * 128;
        outp[(size_t)row * H + c] = (v[i] - mean) * inv * gw[c] + bw[c];
    }
}

// ---------------- driver ----------------
template<int H>
static void launch_rec(const float* Whh) {
    constexpr int SM = sizeof(unsigned) * ((H / 8) * 192 + 8 * 4 * 1024);
    cudaFuncSetAttribute(gru_rec<H>, cudaFuncAttributeMaxDynamicSharedMemorySize, SM);
    gru_rec<H><<<H / 8, 256, SM>>>(Whh);
}

extern "C" void kernel_launch(void* const* d_in, const int* in_sizes, int n_in,
                              void* d_out, int out_size) {
    (void)in_sizes; (void)n_in; (void)out_size;
    const float* x = (const float*)d_in[0];
    const float* Wih[6]; const float* Whh[6]; const float* gw[6]; const float* bw[6];
    for (int l = 0; l < 6; l++) {
        Wih[l] = (const float*)d_in[1 + 4 * l];
        Whh[l] = (const float*)d_in[2 + 4 * l];
        gw[l]  = (const float*)d_in[3 + 4 * l];
        bw[l]  = (const float*)d_in[4 + 4 * l];
    }
    float* actB;
    cudaGetSymbolAddress((void**)&actB, g_actB);

    static const int DIN[6] = {128, 256, 512, 1024, 512, 256};
    static const int HH[6]  = {256, 512, 1024, 512, 256, 128};

    for (int l = 0; l < 6; l++) {
        const int K = DIN[l], H = HH[l], N = 3 * H;
        const float* A = (l == 0) ? x : (const float*)actB;
        const float* gma = (l == 0) ? nullptr : gw[l - 1];
        const float* bta = (l == 0) ? nullptr : bw[l - 1];
        const int nprev = (l == 0) ? 0 : HH[l - 1] / 8;
        dim3 grid(N / 128, 256);
        if (l == 0) {
            gemm_xg<128, false><<<grid, 256>>>(A, Wih[l], N, gma, bta, nprev);
        } else {
            switch (K) {
                case 256:  gemm_xg<256, true><<<grid, 256>>>(A, Wih[l], N, gma, bta, nprev); break;
                case 512:  gemm_xg<512, true><<<grid, 256>>>(A, Wih[l], N, gma, bta, nprev); break;
                case 1024: gemm_xg<1024, true><<<grid, 256>>>(A, Wih[l], N, gma, bta, nprev); break;
            }
        }
        switch (H) {
            case 128:  launch_rec<128>(Whh[l]); break;
            case 256:  launch_rec<256>(Whh[l]); break;
            case 512:  launch_rec<512>(Whh[l]); break;
            case 1024: launch_rec<1024>(Whh[l]); break;
        }
    }
    ln_k<128><<<32768, 128>>>(gw[5], bw[5], (float*)d_out);
}

// round 17
// speedup vs baseline: 1.2222x; 1.0968x over previous
#include <cuda_runtime.h>
#include <cstdint>

// ---------------- static scratch (no allocs allowed) ----------------
__device__ float g_xg[32768 * 3072];        // input-projection buffer (max 3H=3072)
__device__ float g_actB[32768 * 1024];      // raw GRU outputs (pre-LN)
__device__ unsigned g_h[2][64 * 1024];      // double-buffered hidden state (tf32 bits)
__device__ float g_psum[256 * 32768];       // per-CTA partial row sums
__device__ float g_psqs[256 * 32768];       // per-CTA partial row sumsq
__device__ float g_sum[32768];              // reduced row sums
__device__ float g_sqs[32768];              // reduced row sumsq
__device__ unsigned g_arr[256 * 32];        // per-CTA progress flags (128B stride)

// ---------------- helpers ----------------
__device__ __forceinline__ unsigned f2tf(float x) {
    unsigned r; asm("cvt.rna.tf32.f32 %0, %1;" : "=r"(r) : "f"(x)); return r;
}
__device__ __forceinline__ void mma8(float* c, const unsigned* a, const unsigned* b) {
    asm volatile("mma.sync.aligned.m16n8k8.row.col.f32.tf32.tf32.f32 "
                 "{%0,%1,%2,%3}, {%4,%5,%6,%7}, {%8,%9}, {%0,%1,%2,%3};"
                 : "+f"(c[0]), "+f"(c[1]), "+f"(c[2]), "+f"(c[3])
                 : "r"(a[0]), "r"(a[1]), "r"(a[2]), "r"(a[3]),
                   "r"(b[0]), "r"(b[1]));
}
__device__ __forceinline__ float fast_sigmoid(float x) {
    return __fdividef(1.f, 1.f + __expf(-x));
}
__device__ __forceinline__ float fast_tanh(float x) {
    return 1.f - __fdividef(2.f, __expf(2.f * x) + 1.f);
}
__device__ __forceinline__ void cpa16(unsigned* smem_dst, const void* gsrc) {
    unsigned d = (unsigned)__cvta_generic_to_shared(smem_dst);
    asm volatile("cp.async.cg.shared.global [%0], [%1], 16;" :: "r"(d), "l"(gsrc));
}
#define CP_COMMIT() asm volatile("cp.async.commit_group;" ::: "memory")
template<int N> __device__ __forceinline__ void cp_wait() {
    asm volatile("cp.async.wait_group %0;" :: "n"(N) : "memory");
}

// ---------------- input-projection GEMM (128x128 tiles) with optional fused LN ----
// (round-13 verbatim structure; only the flag reset width and LN slot-range changed)
template<int K, bool LN>
__global__ void __launch_bounds__(256) gemm_xg(const float* __restrict__ A,
                                               const float* __restrict__ W,
                                               int N,
                                               const float* __restrict__ gma,
                                               const float* __restrict__ bta,
                                               int nprev, int splitprev) {
    __shared__ unsigned As[128 * 36];
    __shared__ unsigned Bs[128 * 36];
    __shared__ float gS[K], bS[K];
    __shared__ float rmS[128], rsS[128];

    const int m0 = blockIdx.y * 128;
    const int n0 = blockIdx.x * 128;
    const int tid = threadIdx.x;
    const int lane = tid & 31, wid = tid >> 5;
    const int wm = (wid & 3) * 32, wn = (wid >> 2) * 64;

    if (blockIdx.x == 0 && blockIdx.y == 0)
        g_arr[tid * 32] = 0u;              // reset all 256 progress flags

    if (LN) {
        for (int i = tid; i < K; i += 256) { gS[i] = gma[i]; bS[i] = bta[i]; }
        if (tid < 128) {
            int m = m0 + tid;
            int half = (splitprev == 2) ? ((m >> 14) & 1) : 0;
            int base = half * nprev;
            float s, q;
            if ((m & 511) >= 510) {
                s = 0.f; q = 0.f;
                for (int c = base; c < base + nprev; c++) {
                    s += g_psum[(size_t)c * 32768 + m];
                    q += g_psqs[(size_t)c * 32768 + m];
                }
            } else {
                s = g_sum[m]; q = g_sqs[m];
            }
            float mean = s * (1.f / K);
            float var = q * (1.f / K) - mean * mean;
            rmS[tid] = mean;
            rsS[tid] = rsqrtf(var);
        }
        __syncthreads();
    }

    float acc[2][8][4];
#pragma unroll
    for (int i = 0; i < 2; i++)
#pragma unroll
        for (int j = 0; j < 8; j++)
#pragma unroll
            for (int k = 0; k < 4; k++) acc[i][j][k] = 0.f;

    const int lr = tid >> 3;
    const int lc = (tid & 7) * 4;

    for (int kc = 0; kc < K; kc += 32) {
#pragma unroll
        for (int i = 0; i < 4; i++) {
            int r = lr + i * 32;
            float4 v = *reinterpret_cast<const float4*>(&A[(size_t)(m0 + r) * K + kc + lc]);
            if (LN) {
                float mm = rmS[r], ss = rsS[r];
                int k = kc + lc;
                v.x = (v.x - mm) * ss * gS[k]     + bS[k];
                v.y = (v.y - mm) * ss * gS[k + 1] + bS[k + 1];
                v.z = (v.z - mm) * ss * gS[k + 2] + bS[k + 2];
                v.w = (v.w - mm) * ss * gS[k + 3] + bS[k + 3];
            }
            *reinterpret_cast<uint4*>(&As[r * 36 + lc]) =
                make_uint4(f2tf(v.x), f2tf(v.y), f2tf(v.z), f2tf(v.w));
        }
#pragma unroll
        for (int i = 0; i < 4; i++) {
            int r = lr + i * 32;
            float4 v = *reinterpret_cast<const float4*>(&W[(size_t)(n0 + r) * K + kc + lc]);
            *reinterpret_cast<uint4*>(&Bs[r * 36 + lc]) =
                make_uint4(f2tf(v.x), f2tf(v.y), f2tf(v.z), f2tf(v.w));
        }
        __syncthreads();
#pragma unroll
        for (int k8 = 0; k8 < 4; k8++) {
            const int kb = k8 * 8;
            unsigned a[2][4], b[8][2];
#pragma unroll
            for (int mf = 0; mf < 2; mf++) {
                int rb = wm + mf * 16 + (lane >> 2);
                a[mf][0] = As[rb * 36 + kb + (lane & 3)];
                a[mf][1] = As[(rb + 8) * 36 + kb + (lane & 3)];
                a[mf][2] = As[rb * 36 + kb + (lane & 3) + 4];
                a[mf][3] = As[(rb + 8) * 36 + kb + (lane & 3) + 4];
            }
#pragma unroll
            for (int nf = 0; nf < 8; nf++) {
                int cb = wn + nf * 8 + (lane >> 2);
                b[nf][0] = Bs[cb * 36 + kb + (lane & 3)];
                b[nf][1] = Bs[cb * 36 + kb + (lane & 3) + 4];
            }
#pragma unroll
            for (int mf = 0; mf < 2; mf++)
#pragma unroll
                for (int nf = 0; nf < 8; nf++)
                    mma8(acc[mf][nf], a[mf], b[nf]);
        }
        __syncthreads();
    }
#pragma unroll
    for (int mf = 0; mf < 2; mf++)
#pragma unroll
        for (int nf = 0; nf < 8; nf++) {
            int row = m0 + wm + mf * 16 + (lane >> 2);
            int col = n0 + wn + nf * 8 + 2 * (lane & 3);
            g_xg[(size_t)row * N + col]     = acc[mf][nf][0];
            g_xg[(size_t)row * N + col + 1] = acc[mf][nf][1];
            g_xg[(size_t)(row + 8) * N + col]     = acc[mf][nf][2];
            g_xg[(size_t)(row + 8) * N + col + 1] = acc[mf][nf][3];
        }
}

// ---------------- persistent GRU recurrence (round-13 pipeline + batch SPLIT) -----
// grid = (H/8)*SPLIT CTAs. SPLIT=2 (H<=512): CTA owns 8 cols x one 32-row batch
// half; two disjoint barrier groups (independent GRU chains) -> W halves, F stays.
// SPLIT=1 (H=1024): identical to round 13. Per-row arithmetic bitwise-identical.
template<int H, int SPLIT>
__global__ void __launch_bounds__(256, 1) gru_rec(const float* __restrict__ Whh) {
    constexpr int NCH   = H / 128;        // 128-wide global chunks (kq covers 32 each)
    constexpr int NC    = H / 8;          // CTAs per batch-half
    constexpr int GRID  = NC * SPLIT;
    constexpr int D     = 4;
    constexpr int P     = NCH < D ? NCH : D;
    constexpr int MROWS = 64 / SPLIT;     // batch rows owned by this CTA
    constexpr int RPW   = 32 / SPLIT;     // rows per warp (mi half)
    constexpr int MF    = RPW / 16;       // m-frags per warp (2 or 1)
    constexpr int ITER  = RPW / 4;        // cp.async tasks/lane per chunk
    constexpr int SLOTW = RPW * 32;       // words per pipeline slot
    constexpr int EIT   = MROWS / 32;     // epilogue items per thread
    constexpr int HGSS  = MROWS * 40;     // hgS buffer stride (floats)

    extern __shared__ unsigned char smem_raw[];
    unsigned* Wf = reinterpret_cast<unsigned*>(smem_raw);      // [H/8][3][64] packed B
    unsigned* Apriv = Wf + (H / 8) * 192;                      // 8 warps x D x SLOTW
    float* hgS = reinterpret_cast<float*>(Apriv);              // ALIAS: 4 x [MROWS][40]

    const float* xg = g_xg;
    float* y = g_actB;
    const int tid = threadIdx.x;
    const int lane = tid & 31, wid = tid >> 5;
    const int cta = blockIdx.x;                  // global CTA id
    const int half = (SPLIT == 2) ? (cta >= NC ? 1 : 0) : 0;
    const int cg = cta - half * NC;              // column-group within half
    const int c0 = cg * 8;
    const int rowbase = half * MROWS;
    const int q = lane >> 2, r4 = lane & 3;
    const int mi = wid & 1;                      // m-half within CTA rows
    const int kq = wid >> 1;                     // k-quarter within each 128-chunk
    const int kb0 = kq * 32;

    // one-time: Whh slice -> SMEM in fragment-packed tf32 order
    {
        constexpr int nf4 = H / 4;
        for (int idx = tid; idx < 24 * nf4; idx += 256) {
            int nn = idx / nf4;               // 0..23 : gate*8 + j
            int c4 = (idx % nf4) * 4;
            int gate = nn >> 3, j = nn & 7;
            float4 v = *reinterpret_cast<const float4*>(&Whh[(size_t)(gate * H + c0 + j) * H + c4]);
            int kb8 = c4 >> 3;
            int hf = (c4 >> 2) & 1;
            unsigned* base = Wf + (kb8 * 3 + gate) * 64 + j * 8 + hf;
            base[0] = f2tf(v.x); base[2] = f2tf(v.y);
            base[4] = f2tf(v.z); base[6] = f2tf(v.w);
        }
    }
    __syncthreads();

    const int col = tid & 7;             // epilogue: own column
    const int brow = tid >> 3;           // epilogue: local row base 0..31
    float hl[EIT];
#pragma unroll
    for (int i = 0; i < EIT; i++) hl[i] = 0.f;
    float pxr[EIT], pxz[EIT], pxn[EIT];

#define PF_XG(TT) do { \
        _Pragma("unroll") \
        for (int it = 0; it < EIT; it++) { \
            int b_ = rowbase + brow + it * 32; \
            const float* xrow = xg + ((size_t)b_ * 512 + (TT)) * (size_t)(3 * H); \
            pxr[it] = __ldcs(xrow + c0 + col); \
            pxz[it] = __ldcs(xrow + H + c0 + col); \
            pxn[it] = __ldcs(xrow + 2 * H + c0 + col); \
        } } while (0)

    PF_XG(0);

    unsigned* AwBase = Apriv + wid * (D * SLOTW);

#define ISSUE_CHUNK(CH, SLOT) do { \
        unsigned* _sl = AwBase + (SLOT) * SLOTW; \
        _Pragma("unroll") \
        for (int i_ = 0; i_ < ITER; i_++) { \
            int task_ = lane + i_ * 32; \
            int row_ = task_ >> 3, unit_ = task_ & 7; \
            cpa16(_sl + row_ * 32 + ((unit_ ^ (row_ & 7)) << 2), \
                  &hsrc[(size_t)(rowbase + mi * RPW + row_) * H + (CH) * 128 + kb0 + unit_ * 4]); \
        } \
        CP_COMMIT(); \
    } while (0)

    for (int t = 0; t < 512; t++) {
        float acc[MF][3][4];
#pragma unroll
        for (int mf = 0; mf < MF; mf++)
#pragma unroll
            for (int nf = 0; nf < 3; nf++)
#pragma unroll
                for (int k = 0; k < 4; k++) acc[mf][nf][k] = 0.f;

        if (t > 0) {
            const unsigned* hsrc = g_h[t & 1];
#pragma unroll
            for (int s = 0; s < P; s++) ISSUE_CHUNK(s, s);

            for (int ch = 0; ch < NCH; ch++) {
                const int rem = NCH - 1 - ch;
                if (rem >= P)      { cp_wait<P - 1>(); }
                else if (rem == 3) { cp_wait<3>(); }
                else if (rem == 2) { cp_wait<2>(); }
                else if (rem == 1) { cp_wait<1>(); }
                else               { cp_wait<0>(); }
                __syncwarp();
                const unsigned* Ab = AwBase + (ch % D) * SLOTW;
#pragma unroll
                for (int k8 = 0; k8 < 4; k8++) {
                    const int u0 = k8 * 2;
                    const int sw0 = ((u0 ^ q) << 2) + r4;
                    const int sw1 = (((u0 + 1) ^ q) << 2) + r4;
                    const int g8 = ch * 16 + kq * 4 + k8;
                    unsigned a[MF][4];
#pragma unroll
                    for (int mf = 0; mf < MF; mf++) {
                        a[mf][0] = Ab[(mf * 16 + q) * 32 + sw0];
                        a[mf][1] = Ab[(mf * 16 + q + 8) * 32 + sw0];
                        a[mf][2] = Ab[(mf * 16 + q) * 32 + sw1];
                        a[mf][3] = Ab[(mf * 16 + q + 8) * 32 + sw1];
                    }
#pragma unroll
                    for (int nf = 0; nf < 3; nf++) {
                        uint2 bb = *reinterpret_cast<const uint2*>(&Wf[(g8 * 3 + nf) * 64 + lane * 2]);
                        unsigned bfr[2] = {bb.x, bb.y};
#pragma unroll
                        for (int mf = 0; mf < MF; mf++)
                            mma8(acc[mf][nf], a[mf], bfr);
                    }
                }
                if (ch + P < NCH) ISSUE_CHUNK(ch + P, (ch + P) % D);
            }
        }
        __syncthreads();                 // A slots dead before hgS alias writes

        // ---- all warps store their K-partials into their kq buffer ----
        {
            float* dst = hgS + kq * HGSS;
#pragma unroll
            for (int mf = 0; mf < MF; mf++)
#pragma unroll
                for (int nf = 0; nf < 3; nf++) {
                    int row = mi * RPW + mf * 16 + q;
                    int cc = nf * 8 + 2 * r4;
                    dst[row * 40 + cc]           = acc[mf][nf][0];
                    dst[row * 40 + cc + 1]       = acc[mf][nf][1];
                    dst[(row + 8) * 40 + cc]     = acc[mf][nf][2];
                    dst[(row + 8) * 40 + cc + 1] = acc[mf][nf][3];
                }
        }
        __syncthreads();

        // ---- gate epilogue: sums 4 kq buffers in kq order ----
        unsigned* hdst = g_h[(t + 1) & 1];
#pragma unroll
        for (int it = 0; it < EIT; it++) {
            int loc = brow + it * 32;
            int gb = rowbase + loc;
            float hr = hgS[loc * 40 + col]          + hgS[HGSS + loc * 40 + col]
                     + hgS[2 * HGSS + loc * 40 + col]     + hgS[3 * HGSS + loc * 40 + col];
            float hz = hgS[loc * 40 + 8 + col]      + hgS[HGSS + loc * 40 + 8 + col]
                     + hgS[2 * HGSS + loc * 40 + 8 + col] + hgS[3 * HGSS + loc * 40 + 8 + col];
            float hn = hgS[loc * 40 + 16 + col]     + hgS[HGSS + loc * 40 + 16 + col]
                     + hgS[2 * HGSS + loc * 40 + 16 + col] + hgS[3 * HGSS + loc * 40 + 16 + col];
            float r = fast_sigmoid(pxr[it] + hr);
            float z = fast_sigmoid(pxz[it] + hz);
            float n = fast_tanh(pxn[it] + r * hn);
            float h2 = (1.f - z) * n + z * hl[it];
            hl[it] = h2;
            size_t m = (size_t)gb * 512 + t;
            y[m * (size_t)H + c0 + col] = h2;
            __stcg(&hdst[gb * H + c0 + col], f2tf(h2));
            float s = h2, qq = h2 * h2;
#pragma unroll
            for (int o = 4; o > 0; o >>= 1) {
                s  += __shfl_down_sync(0xffffffffu, s, o, 8);
                qq += __shfl_down_sync(0xffffffffu, qq, o, 8);
            }
            if (col == 0) {
                __stcg(&g_psum[(size_t)cta * 32768 + m], s);
                __stcg(&g_psqs[(size_t)cta * 32768 + m], qq);
            }
        }

        if (t < 511) {
            PF_XG(t + 1);                  // independent of h; hides under barrier
            __syncthreads();               // h stores + hgS reads complete
            if (tid == 0)
                asm volatile("st.release.gpu.u32 [%0], %1;"
                             :: "l"(&g_arr[cta * 32]), "r"((unsigned)(t + 1)) : "memory");
            if (tid < NC) {
                // wait only for this half's NC producers
                const unsigned* fp = &g_arr[(half * NC + tid) * 32];
                unsigned v;
                do {
                    asm volatile("ld.acquire.gpu.u32 %0, [%1];"
                                 : "=r"(v) : "l"(fp) : "memory");
                } while (v < (unsigned)(t + 1));
            } else if (wid >= 4 && t >= 1) {
                // shadow: reduce LN partials of step t-1 while pollers spin
                int r = cta + (wid - 4) * GRID;
                if (r < 64) {
                    int halfR = (SPLIT == 2) ? (r >> 5) : 0;
                    int base = halfR * NC;
                    int m = r * 512 + (t - 1);
                    float s = 0.f, qv = 0.f;
                    for (int c = base + lane; c < base + NC; c += 32) {
                        s  += __ldcg(&g_psum[(size_t)c * 32768 + m]);
                        qv += __ldcg(&g_psqs[(size_t)c * 32768 + m]);
                    }
#pragma unroll
                    for (int o = 16; o > 0; o >>= 1) {
                        s  += __shfl_xor_sync(0xffffffffu, s, o);
                        qv += __shfl_xor_sync(0xffffffffu, qv, o);
                    }
                    if (lane == 0) { __stcg(&g_sum[m], s); __stcg(&g_sqs[m], qv); }
                }
            }
            __syncthreads();
        }
    }
#undef PF_XG
#undef ISSUE_CHUNK
}

// ---------------- final LayerNorm (H=128, eps=0) ----------------
template<int H>
__global__ void __launch_bounds__(128) ln_k(const float* __restrict__ gw,
                                            const float* __restrict__ bw,
                                            float* __restrict__ outp) {
    constexpr int PER = H / 128;
    __shared__ float red[8];
    const int row = blockIdx.x, tid = threadIdx.x;
    const float* p = g_actB + (size_t)row * H;
    float v[PER];
    float s = 0.f;
#pragma unroll
    for (int i = 0; i < PER; i++) { v[i] = p[tid + i * 128]; s += v[i]; }
#pragma unroll
    for (int o = 16; o > 0; o >>= 1) s += __shfl_xor_sync(0xffffffffu, s, o);
    if ((tid & 31) == 0) red[tid >> 5] = s;
    __syncthreads();
    float mean = (red[0] + red[1] + red[2] + red[3]) * (1.f / H);
    float s2 = 0.f;
#pragma unroll
    for (int i = 0; i < PER; i++) { float d = v[i] - mean; s2 += d * d; }
#pragma unroll
    for (int o = 16; o > 0; o >>= 1) s2 += __shfl_xor_sync(0xffffffffu, s2, o);
    if ((tid & 31) == 0) red[4 + (tid >> 5)] = s2;
    __syncthreads();
    float var = (red[4] + red[5] + red[6] + red[7]) * (1.f / H);
    float inv = rsqrtf(var);
#pragma unroll
    for (int i = 0; i < PER; i++) {
        int c = tid + i * 128;
        outp[(size_t)row * H + c] = (v[i] - mean) * inv * gw[c] + bw[c];
    }
}

// ---------------- driver ----------------
template<int H, int SPLIT>
static void launch_rec(const float* Whh) {
    constexpr int SLOTW = (32 / SPLIT) * 32;
    constexpr int SM = sizeof(unsigned) * ((H / 8) * 192 + 8 * 4 * SLOTW);
    cudaFuncSetAttribute(gru_rec<H, SPLIT>, cudaFuncAttributeMaxDynamicSharedMemorySize, SM);
    gru_rec<H, SPLIT><<<(H / 8) * SPLIT, 256, SM>>>(Whh);
}

extern "C" void kernel_launch(void* const* d_in, const int* in_sizes, int n_in,
                              void* d_out, int out_size) {
    (void)in_sizes; (void)n_in; (void)out_size;
    const float* x = (const float*)d_in[0];
    const float* Wih[6]; const float* Whh[6]; const float* gw[6]; const float* bw[6];
    for (int l = 0; l < 6; l++) {
        Wih[l] = (const float*)d_in[1 + 4 * l];
        Whh[l] = (const float*)d_in[2 + 4 * l];
        gw[l]  = (const float*)d_in[3 + 4 * l];
        bw[l]  = (const float*)d_in[4 + 4 * l];
    }
    float* actB;
    cudaGetSymbolAddress((void**)&actB, g_actB);

    static const int DIN[6] = {128, 256, 512, 1024, 512, 256};
    static const int HH[6]  = {256, 512, 1024, 512, 256, 128};
    static const int SPL[6] = {2, 2, 1, 2, 2, 2};

    for (int l = 0; l < 6; l++) {
        const int K = DIN[l], H = HH[l], N = 3 * H;
        const float* A = (l == 0) ? x : (const float*)actB;
        const float* gma = (l == 0) ? nullptr : gw[l - 1];
        const float* bta = (l == 0) ? nullptr : bw[l - 1];
        const int nprev = (l == 0) ? 0 : HH[l - 1] / 8;
        const int splitprev = (l == 0) ? 1 : SPL[l - 1];
        dim3 grid(N / 128, 256);
        if (l == 0) {
            gemm_xg<128, false><<<grid, 256>>>(A, Wih[l], N, gma, bta, nprev, splitprev);
        } else {
            switch (K) {
                case 256:  gemm_xg<256, true><<<grid, 256>>>(A, Wih[l], N, gma, bta, nprev, splitprev); break;
                case 512:  gemm_xg<512, true><<<grid, 256>>>(A, Wih[l], N, gma, bta, nprev, splitprev); break;
                case 1024: gemm_xg<1024, true><<<grid, 256>>>(A, Wih[l], N, gma, bta, nprev, splitprev); break;
            }
        }
        switch (H) {
            case 128:  launch_rec<128, 2>(Whh[l]); break;
            case 256:  launch_rec<256, 2>(Whh[l]); break;
            case 512:  launch_rec<512, 2>(Whh[l]); break;
            case 1024: launch_rec<1024, 1>(Whh[l]); break;
        }
    }
    ln_k<128><<<32768, 128>>>(gw[5], bw[5], (float*)d_out);
}